// round 4
// baseline (speedup 1.0000x reference)
#include <cuda_runtime.h>
#include <math.h>

#define L 5
#define C 16
#define H 256
#define W 256
#define HW (H*W)
#define BN_EPS 1e-5f

// Folded parameters computed once per launch by prep_kernel.
struct Params {
    float minv[L*L][6];    // [a*L+b]: inverse affine of T[a][b] (rows of 2x3)
    float w1nb[16][16];    // layer1 weights acting on nb channels (BN-folded)
    float w1eg[16][16];    // layer1 weights acting on ego channels (BN-folded)
    float b1[16];
    float w2[8][16];
    float b2[8];
    float w3[4][8];
    float b3[4];
    float w4[4];
    float b4;
    float wm[16][16];
    float bm[16];
};
__device__ Params g_p;

__global__ void prep_kernel(
    const float* __restrict__ ptm,
    const float* __restrict__ w1, const float* __restrict__ b1,
    const float* __restrict__ g1, const float* __restrict__ be1,
    const float* __restrict__ rm1, const float* __restrict__ rv1,
    const float* __restrict__ w2, const float* __restrict__ b2,
    const float* __restrict__ g2, const float* __restrict__ be2,
    const float* __restrict__ rm2, const float* __restrict__ rv2,
    const float* __restrict__ w3, const float* __restrict__ b3,
    const float* __restrict__ g3, const float* __restrict__ be3,
    const float* __restrict__ rm3, const float* __restrict__ rv3,
    const float* __restrict__ w4, const float* __restrict__ b4,
    const float* __restrict__ wm, const float* __restrict__ bm)
{
    int t = threadIdx.x;

    // ---- inverse affines for all 25 (a,b) pairs ----
    if (t < L*L) {
        const float* m = ptm + t*16;           // 4x4 row-major
        float a  = m[0], b = m[1], tx = m[3] * 1.25f;   // 1/(0.4*2)
        float c  = m[4], d = m[5], ty = m[7] * 1.25f;
        float inv = 1.0f / (a*d - b*c);
        float ia =  d*inv, ib = -b*inv;
        float ic = -c*inv, id =  a*inv;
        g_p.minv[t][0] = ia; g_p.minv[t][1] = ib; g_p.minv[t][2] = -(ia*tx + ib*ty);
        g_p.minv[t][3] = ic; g_p.minv[t][4] = id; g_p.minv[t][5] = -(ic*tx + id*ty);
    }
    // ---- layer 1 (32->16), BN folded, split nb/ego ----
    if (t >= 32 && t < 48) {
        int o = t - 32;
        float sc = g1[o] * rsqrtf(rv1[o] + BN_EPS);
        for (int c2 = 0; c2 < 16; c2++) g_p.w1nb[o][c2] = w1[o*32 + c2]      * sc;
        for (int c2 = 0; c2 < 16; c2++) g_p.w1eg[o][c2] = w1[o*32 + 16 + c2] * sc;
        g_p.b1[o] = (b1[o] - rm1[o]) * sc + be1[o];
    }
    // ---- layer 2 (16->8) ----
    if (t >= 48 && t < 56) {
        int o = t - 48;
        float sc = g2[o] * rsqrtf(rv2[o] + BN_EPS);
        for (int c2 = 0; c2 < 16; c2++) g_p.w2[o][c2] = w2[o*16 + c2] * sc;
        g_p.b2[o] = (b2[o] - rm2[o]) * sc + be2[o];
    }
    // ---- layer 3 (8->4) ----
    if (t >= 56 && t < 60) {
        int o = t - 56;
        float sc = g3[o] * rsqrtf(rv3[o] + BN_EPS);
        for (int c2 = 0; c2 < 8; c2++) g_p.w3[o][c2] = w3[o*8 + c2] * sc;
        g_p.b3[o] = (b3[o] - rm3[o]) * sc + be3[o];
    }
    // ---- layer 4 (4->1), no BN ----
    if (t == 60) {
        for (int c2 = 0; c2 < 4; c2++) g_p.w4[c2] = w4[c2];
        g_p.b4 = b4[0];
    }
    // ---- final channel mix ----
    if (t >= 64 && t < 80) {
        int o = t - 64;
        for (int c2 = 0; c2 < 16; c2++) g_p.wm[o][c2] = wm[o*16 + c2];
        g_p.bm[o] = bm[o];
    }
}

__global__ __launch_bounds__(256)
void DiscoNetFusion_kernel(const float* __restrict__ x, float* __restrict__ out)
{
    __shared__ Params sp;
    {
        const float* src = (const float*)&g_p;
        float* dst = (float*)&sp;
        const int n = sizeof(Params) / 4;
        for (int k = threadIdx.x; k < n; k += blockDim.x) dst[k] = src[k];
    }
    __syncthreads();

    const int i  = blockIdx.y;                          // ego agent
    const int hw = blockIdx.x * blockDim.x + threadIdx.x;
    const float wf = (float)(hw & (W-1));
    const float hf = (float)(hw >> 8);

    // ---- ego precompute: w1eg @ x_i + b1 (j-invariant part of layer1) ----
    float ego[16];
    {
        float xi[16];
        #pragma unroll
        for (int c = 0; c < 16; c++) xi[c] = x[(i*C + c)*HW + hw];
        #pragma unroll
        for (int o = 0; o < 16; o++) {
            float a = sp.b1[o];
            #pragma unroll
            for (int c = 0; c < 16; c++) a = fmaf(sp.w1eg[o][c], xi[c], a);
            ego[o] = a;
        }
    }

    // ---- online softmax state over j ----
    float mrun = -1e30f, srun = 0.0f;
    float acc[16];
    #pragma unroll
    for (int c = 0; c < 16; c++) acc[c] = 0.0f;

    #pragma unroll 1
    for (int j = 0; j < L; j++) {
        // nb[i][j] = warp(x[j], T[j][i]) at this pixel
        const float* mv = sp.minv[j*L + i];
        float sx = fmaf(mv[0], wf, fmaf(mv[1], hf, mv[2]));
        float sy = fmaf(mv[3], wf, fmaf(mv[4], hf, mv[5]));
        float x0f = floorf(sx), y0f = floorf(sy);
        float fx = sx - x0f, fy = sy - y0f;
        float w00 = (1.0f-fx)*(1.0f-fy), w01 = fx*(1.0f-fy);
        float w10 = (1.0f-fx)*fy,        w11 = fx*fy;
        int x0 = (int)x0f, y0 = (int)y0f;
        bool vx0 = (x0   >= 0) && (x0   <= W-1);
        bool vx1 = (x0+1 >= 0) && (x0+1 <= W-1);
        bool vy0 = (y0   >= 0) && (y0   <= H-1);
        bool vy1 = (y0+1 >= 0) && (y0+1 <= H-1);
        if (!(vx0 && vy0)) w00 = 0.0f;
        if (!(vx1 && vy0)) w01 = 0.0f;
        if (!(vx0 && vy1)) w10 = 0.0f;
        if (!(vx1 && vy1)) w11 = 0.0f;
        int xi0 = min(max(x0,   0), W-1), xi1 = min(max(x0+1, 0), W-1);
        int yi0 = min(max(y0,   0), H-1), yi1 = min(max(y0+1, 0), H-1);
        const float* base = x + (size_t)j*C*HW;
        int o00 = yi0*W + xi0, o01 = yi0*W + xi1;
        int o10 = yi1*W + xi0, o11 = yi1*W + xi1;

        float nb[16];
        #pragma unroll
        for (int c = 0; c < 16; c++) {
            const float* p = base + c*HW;
            nb[c] = fmaf(w00, __ldg(p + o00),
                    fmaf(w01, __ldg(p + o01),
                    fmaf(w10, __ldg(p + o10),
                          w11 * __ldg(p + o11))));
        }

        // ---- tiny MLP -> logit ----
        float h1[16];
        #pragma unroll
        for (int o = 0; o < 16; o++) {
            float a = ego[o];
            #pragma unroll
            for (int c = 0; c < 16; c++) a = fmaf(sp.w1nb[o][c], nb[c], a);
            h1[o] = fmaxf(a, 0.0f);
        }
        float h2[8];
        #pragma unroll
        for (int o = 0; o < 8; o++) {
            float a = sp.b2[o];
            #pragma unroll
            for (int c = 0; c < 16; c++) a = fmaf(sp.w2[o][c], h1[c], a);
            h2[o] = fmaxf(a, 0.0f);
        }
        float h3[4];
        #pragma unroll
        for (int o = 0; o < 4; o++) {
            float a = sp.b3[o];
            #pragma unroll
            for (int c = 0; c < 8; c++) a = fmaf(sp.w3[o][c], h2[c], a);
            h3[o] = fmaxf(a, 0.0f);
        }
        float lg = sp.b4;
        #pragma unroll
        for (int c = 0; c < 4; c++) lg = fmaf(sp.w4[c], h3[c], lg);
        lg = fmaxf(lg, 0.0f);

        // ---- online softmax accumulate ----
        float mn  = fmaxf(mrun, lg);
        float scl = __expf(mrun - mn);
        float p   = __expf(lg - mn);
        srun = srun * scl + p;
        #pragma unroll
        for (int c = 0; c < 16; c++) acc[c] = fmaf(acc[c], scl, p * nb[c]);
        mrun = mn;
    }

    const float invs = 1.0f / srun;
    #pragma unroll
    for (int c = 0; c < 16; c++) acc[c] *= invs;

    // ---- final 16x16 channel mix + bias ----
    #pragma unroll
    for (int o = 0; o < 16; o++) {
        float a = sp.bm[o];
        #pragma unroll
        for (int c = 0; c < 16; c++) a = fmaf(sp.wm[o][c], acc[c], a);
        out[(i*C + o)*HW + hw] = a;
    }
}

extern "C" void kernel_launch(void* const* d_in, const int* in_sizes, int n_in,
                              void* d_out, int out_size)
{
    (void)in_sizes; (void)n_in; (void)out_size;
    const float* x   = (const float*)d_in[0];
    // d_in[1] = record_len (unused)
    const float* ptm = (const float*)d_in[2];

    prep_kernel<<<1, 128>>>(ptm,
        (const float*)d_in[3],  (const float*)d_in[4],  (const float*)d_in[5],
        (const float*)d_in[6],  (const float*)d_in[7],  (const float*)d_in[8],
        (const float*)d_in[9],  (const float*)d_in[10], (const float*)d_in[11],
        (const float*)d_in[12], (const float*)d_in[13], (const float*)d_in[14],
        (const float*)d_in[15], (const float*)d_in[16], (const float*)d_in[17],
        (const float*)d_in[18], (const float*)d_in[19], (const float*)d_in[20],
        (const float*)d_in[21], (const float*)d_in[22],
        (const float*)d_in[23], (const float*)d_in[24]);

    dim3 grid(HW / 256, L);
    DiscoNetFusion_kernel<<<grid, 256>>>(x, (float*)d_out);
}

// round 5
// speedup vs baseline: 1.0915x; 1.0915x over previous
#include <cuda_runtime.h>
#include <cuda_fp16.h>
#include <math.h>

#define L 5
#define C 16
#define H 256
#define W 256
#define HW (H*W)
#define BN_EPS 1e-5f

// Folded parameters computed once per launch by prep_kernel.
struct Params {
    float minv[L*L][6];    // [a*L+b]: inverse affine of T[a][b] (rows of 2x3)
    float w1nb[16][16];    // layer1 weights acting on nb channels (BN-folded)
    float w1eg[16][16];    // layer1 weights acting on ego channels (BN-folded)
    float b1[16];
    float w2[8][16];
    float b2[8];
    float w3[4][8];
    float b3[4];
    float w4[4];
    float b4;
    float wm[16][16];
    float bm[16];
};
__device__ Params g_p;

// HWC fp16 copy of x: per pixel, 16 channels = 8 half2 = 32 bytes contiguous.
// 5 * 65536 * 8 * 4B = 10.5 MB static scratch (allowed: __device__ global array).
__device__ __half2 g_xt[(size_t)L * HW * 8];

__global__ void prep_kernel(
    const float* __restrict__ ptm,
    const float* __restrict__ w1, const float* __restrict__ b1,
    const float* __restrict__ g1, const float* __restrict__ be1,
    const float* __restrict__ rm1, const float* __restrict__ rv1,
    const float* __restrict__ w2, const float* __restrict__ b2,
    const float* __restrict__ g2, const float* __restrict__ be2,
    const float* __restrict__ rm2, const float* __restrict__ rv2,
    const float* __restrict__ w3, const float* __restrict__ b3,
    const float* __restrict__ g3, const float* __restrict__ be3,
    const float* __restrict__ rm3, const float* __restrict__ rv3,
    const float* __restrict__ w4, const float* __restrict__ b4,
    const float* __restrict__ wm, const float* __restrict__ bm)
{
    int t = threadIdx.x;

    if (t < L*L) {
        const float* m = ptm + t*16;           // 4x4 row-major
        float a  = m[0], b = m[1], tx = m[3] * 1.25f;   // 1/(0.4*2)
        float c  = m[4], d = m[5], ty = m[7] * 1.25f;
        float inv = 1.0f / (a*d - b*c);
        float ia =  d*inv, ib = -b*inv;
        float ic = -c*inv, id =  a*inv;
        g_p.minv[t][0] = ia; g_p.minv[t][1] = ib; g_p.minv[t][2] = -(ia*tx + ib*ty);
        g_p.minv[t][3] = ic; g_p.minv[t][4] = id; g_p.minv[t][5] = -(ic*tx + id*ty);
    }
    if (t >= 32 && t < 48) {
        int o = t - 32;
        float sc = g1[o] * rsqrtf(rv1[o] + BN_EPS);
        for (int c2 = 0; c2 < 16; c2++) g_p.w1nb[o][c2] = w1[o*32 + c2]      * sc;
        for (int c2 = 0; c2 < 16; c2++) g_p.w1eg[o][c2] = w1[o*32 + 16 + c2] * sc;
        g_p.b1[o] = (b1[o] - rm1[o]) * sc + be1[o];
    }
    if (t >= 48 && t < 56) {
        int o = t - 48;
        float sc = g2[o] * rsqrtf(rv2[o] + BN_EPS);
        for (int c2 = 0; c2 < 16; c2++) g_p.w2[o][c2] = w2[o*16 + c2] * sc;
        g_p.b2[o] = (b2[o] - rm2[o]) * sc + be2[o];
    }
    if (t >= 56 && t < 60) {
        int o = t - 56;
        float sc = g3[o] * rsqrtf(rv3[o] + BN_EPS);
        for (int c2 = 0; c2 < 8; c2++) g_p.w3[o][c2] = w3[o*8 + c2] * sc;
        g_p.b3[o] = (b3[o] - rm3[o]) * sc + be3[o];
    }
    if (t == 60) {
        for (int c2 = 0; c2 < 4; c2++) g_p.w4[c2] = w4[c2];
        g_p.b4 = b4[0];
    }
    if (t >= 64 && t < 80) {
        int o = t - 64;
        for (int c2 = 0; c2 < 16; c2++) g_p.wm[o][c2] = wm[o*16 + c2];
        g_p.bm[o] = bm[o];
    }
}

// CHW fp32 -> HWC fp16 transpose. Reads coalesced per-channel, writes 32B/pixel.
__global__ __launch_bounds__(256)
void transpose_kernel(const float* __restrict__ x)
{
    int idx = blockIdx.x * 256 + threadIdx.x;   // over L*HW
    int j   = idx >> 16;
    int hw  = idx & (HW - 1);
    const float* base = x + (size_t)j * C * HW + hw;

    __half2 v[8];
    #pragma unroll
    for (int k = 0; k < 8; k++) {
        float a = __ldg(base + (2*k)   * HW);
        float b = __ldg(base + (2*k+1) * HW);
        v[k] = __floats2half2_rn(a, b);
    }
    uint4* dst = reinterpret_cast<uint4*>(g_xt) + (size_t)idx * 2;
    dst[0] = reinterpret_cast<uint4*>(v)[0];
    dst[1] = reinterpret_cast<uint4*>(v)[1];
}

__device__ __forceinline__ void acc_tap(uint4 v, float wgt, float2* nb2)
{
    #pragma unroll
    for (int k = 0; k < 4; k++) {
        __half2 h = reinterpret_cast<__half2*>(&v)[k];
        float2 f = __half22float2(h);
        nb2[k].x = fmaf(wgt, f.x, nb2[k].x);
        nb2[k].y = fmaf(wgt, f.y, nb2[k].y);
    }
}

__global__ __launch_bounds__(256)
void DiscoNetFusion_kernel(const float* __restrict__ x, float* __restrict__ out)
{
    __shared__ Params sp;
    {
        const float* src = (const float*)&g_p;
        float* dst = (float*)&sp;
        const int n = sizeof(Params) / 4;
        for (int k = threadIdx.x; k < n; k += blockDim.x) dst[k] = src[k];
    }
    __syncthreads();

    const int i  = blockIdx.y;                          // ego agent
    const int hw = blockIdx.x * blockDim.x + threadIdx.x;
    const float wf = (float)(hw & (W-1));
    const float hf = (float)(hw >> 8);

    // ---- ego precompute: w1eg @ x_i + b1 (fp32, coalesced CHW loads) ----
    float ego[16];
    {
        float xi[16];
        #pragma unroll
        for (int c = 0; c < 16; c++) xi[c] = x[(i*C + c)*HW + hw];
        #pragma unroll
        for (int o = 0; o < 16; o++) {
            float a = sp.b1[o];
            #pragma unroll
            for (int c = 0; c < 16; c++) a = fmaf(sp.w1eg[o][c], xi[c], a);
            ego[o] = a;
        }
    }

    // ---- online softmax state over j ----
    float mrun = -1e30f, srun = 0.0f;
    float acc[16];
    #pragma unroll
    for (int c = 0; c < 16; c++) acc[c] = 0.0f;

    #pragma unroll 1
    for (int j = 0; j < L; j++) {
        const float* mv = sp.minv[j*L + i];
        float sx = fmaf(mv[0], wf, fmaf(mv[1], hf, mv[2]));
        float sy = fmaf(mv[3], wf, fmaf(mv[4], hf, mv[5]));
        float x0f = floorf(sx), y0f = floorf(sy);
        float fx = sx - x0f, fy = sy - y0f;
        float w00 = (1.0f-fx)*(1.0f-fy), w01 = fx*(1.0f-fy);
        float w10 = (1.0f-fx)*fy,        w11 = fx*fy;
        int x0 = (int)x0f, y0 = (int)y0f;
        bool vx0 = (x0   >= 0) && (x0   <= W-1);
        bool vx1 = (x0+1 >= 0) && (x0+1 <= W-1);
        bool vy0 = (y0   >= 0) && (y0   <= H-1);
        bool vy1 = (y0+1 >= 0) && (y0+1 <= H-1);
        if (!(vx0 && vy0)) w00 = 0.0f;
        if (!(vx1 && vy0)) w01 = 0.0f;
        if (!(vx0 && vy1)) w10 = 0.0f;
        if (!(vx1 && vy1)) w11 = 0.0f;
        int xi0 = min(max(x0,   0), W-1), xi1 = min(max(x0+1, 0), W-1);
        int yi0 = min(max(y0,   0), H-1), yi1 = min(max(y0+1, 0), H-1);

        // HWC fp16 taps: 2 x uint4 (32B = 16 channels) per tap
        const uint4* jb = reinterpret_cast<const uint4*>(
                              g_xt + (size_t)j * HW * 8);
        const uint4* p00 = jb + (size_t)(yi0*W + xi0) * 2;
        const uint4* p01 = jb + (size_t)(yi0*W + xi1) * 2;
        const uint4* p10 = jb + (size_t)(yi1*W + xi0) * 2;
        const uint4* p11 = jb + (size_t)(yi1*W + xi1) * 2;
        uint4 t00a = __ldg(p00),     t00b = __ldg(p00 + 1);
        uint4 t01a = __ldg(p01),     t01b = __ldg(p01 + 1);
        uint4 t10a = __ldg(p10),     t10b = __ldg(p10 + 1);
        uint4 t11a = __ldg(p11),     t11b = __ldg(p11 + 1);

        float2 nb2[8];
        #pragma unroll
        for (int k = 0; k < 8; k++) { nb2[k].x = 0.0f; nb2[k].y = 0.0f; }
        acc_tap(t00a, w00, nb2);     acc_tap(t00b, w00, nb2 + 4);
        acc_tap(t01a, w01, nb2);     acc_tap(t01b, w01, nb2 + 4);
        acc_tap(t10a, w10, nb2);     acc_tap(t10b, w10, nb2 + 4);
        acc_tap(t11a, w11, nb2);     acc_tap(t11b, w11, nb2 + 4);
        const float* nb = reinterpret_cast<const float*>(nb2);

        // ---- tiny MLP -> logit ----
        float h1[16];
        #pragma unroll
        for (int o = 0; o < 16; o++) {
            float a = ego[o];
            #pragma unroll
            for (int c = 0; c < 16; c++) a = fmaf(sp.w1nb[o][c], nb[c], a);
            h1[o] = fmaxf(a, 0.0f);
        }
        float h2[8];
        #pragma unroll
        for (int o = 0; o < 8; o++) {
            float a = sp.b2[o];
            #pragma unroll
            for (int c = 0; c < 16; c++) a = fmaf(sp.w2[o][c], h1[c], a);
            h2[o] = fmaxf(a, 0.0f);
        }
        float h3[4];
        #pragma unroll
        for (int o = 0; o < 4; o++) {
            float a = sp.b3[o];
            #pragma unroll
            for (int c = 0; c < 8; c++) a = fmaf(sp.w3[o][c], h2[c], a);
            h3[o] = fmaxf(a, 0.0f);
        }
        float lg = sp.b4;
        #pragma unroll
        for (int c = 0; c < 4; c++) lg = fmaf(sp.w4[c], h3[c], lg);
        lg = fmaxf(lg, 0.0f);

        // ---- online softmax accumulate ----
        float mn  = fmaxf(mrun, lg);
        float scl = __expf(mrun - mn);
        float p   = __expf(lg - mn);
        srun = srun * scl + p;
        #pragma unroll
        for (int c = 0; c < 16; c++) acc[c] = fmaf(acc[c], scl, p * nb[c]);
        mrun = mn;
    }

    const float invs = 1.0f / srun;
    #pragma unroll
    for (int c = 0; c < 16; c++) acc[c] *= invs;

    // ---- final 16x16 channel mix + bias ----
    #pragma unroll
    for (int o = 0; o < 16; o++) {
        float a = sp.bm[o];
        #pragma unroll
        for (int c = 0; c < 16; c++) a = fmaf(sp.wm[o][c], acc[c], a);
        out[(i*C + o)*HW + hw] = a;
    }
}

extern "C" void kernel_launch(void* const* d_in, const int* in_sizes, int n_in,
                              void* d_out, int out_size)
{
    (void)in_sizes; (void)n_in; (void)out_size;
    const float* x   = (const float*)d_in[0];
    // d_in[1] = record_len (unused)
    const float* ptm = (const float*)d_in[2];

    prep_kernel<<<1, 128>>>(ptm,
        (const float*)d_in[3],  (const float*)d_in[4],  (const float*)d_in[5],
        (const float*)d_in[6],  (const float*)d_in[7],  (const float*)d_in[8],
        (const float*)d_in[9],  (const float*)d_in[10], (const float*)d_in[11],
        (const float*)d_in[12], (const float*)d_in[13], (const float*)d_in[14],
        (const float*)d_in[15], (const float*)d_in[16], (const float*)d_in[17],
        (const float*)d_in[18], (const float*)d_in[19], (const float*)d_in[20],
        (const float*)d_in[21], (const float*)d_in[22],
        (const float*)d_in[23], (const float*)d_in[24]);

    transpose_kernel<<<(L*HW)/256, 256>>>(x);

    dim3 grid(HW / 256, L);
    DiscoNetFusion_kernel<<<grid, 256>>>(x, (float*)d_out);
}

// round 8
// speedup vs baseline: 1.1997x; 1.0991x over previous
#include <cuda_runtime.h>
#include <cuda_fp16.h>
#include <math.h>

#define L 5
#define C 16
#define H 256
#define W 256
#define HW (H*W)
#define BN_EPS 1e-5f

typedef unsigned long long u64;

// ---- packed fp32x2 helpers (Blackwell FFMA2 path) ----
__device__ __forceinline__ u64 f2u(float2 v) {
    u64 r; asm("mov.b64 %0, {%1,%2};" : "=l"(r) : "f"(v.x), "f"(v.y)); return r;
}
__device__ __forceinline__ float2 u2f(u64 v) {
    float2 r; asm("mov.b64 {%0,%1}, %2;" : "=f"(r.x), "=f"(r.y) : "l"(v)); return r;
}
__device__ __forceinline__ float2 ffma2(float2 a, float2 b, float2 c) {
    u64 d;
    asm("fma.rn.f32x2 %0, %1, %2, %3;" : "=l"(d) : "l"(f2u(a)), "l"(f2u(b)), "l"(f2u(c)));
    return u2f(d);
}
__device__ __forceinline__ float2 fmul2(float2 a, float2 b) {
    u64 d;
    asm("mul.rn.f32x2 %0, %1, %2;" : "=l"(d) : "l"(f2u(a)), "l"(f2u(b)));
    return u2f(d);
}

// Folded parameters. All weight arrays 16B-aligned for LDS.128.
struct __align__(16) Params {
    float minv[L*L][8];    // rows of inverse 2x3 affine (padded to 32B)
    float w1nb[16][16];
    float w1eg[16][16];
    float b1[16];
    float w2[8][16];
    float b2[8];
    float w3[4][8];
    float b3[4];
    float w4[4];
    float b4;
    float _pad[3];
    float wm[16][16];
    float bm[16];
};
__device__ Params g_p;

// HWC fp16 copy of x: per pixel, 16 channels = 32 bytes contiguous. 10.5 MB.
__device__ __half2 g_xt[(size_t)L * HW * 8];

__global__ void prep_kernel(
    const float* __restrict__ ptm,
    const float* __restrict__ w1, const float* __restrict__ b1,
    const float* __restrict__ g1, const float* __restrict__ be1,
    const float* __restrict__ rm1, const float* __restrict__ rv1,
    const float* __restrict__ w2, const float* __restrict__ b2,
    const float* __restrict__ g2, const float* __restrict__ be2,
    const float* __restrict__ rm2, const float* __restrict__ rv2,
    const float* __restrict__ w3, const float* __restrict__ b3,
    const float* __restrict__ g3, const float* __restrict__ be3,
    const float* __restrict__ rm3, const float* __restrict__ rv3,
    const float* __restrict__ w4, const float* __restrict__ b4,
    const float* __restrict__ wm, const float* __restrict__ bm)
{
    int t = threadIdx.x;

    if (t < L*L) {
        const float* m = ptm + t*16;           // 4x4 row-major
        float a  = m[0], b = m[1], tx = m[3] * 1.25f;   // 1/(0.4*2)
        float c  = m[4], d = m[5], ty = m[7] * 1.25f;
        float inv = 1.0f / (a*d - b*c);
        float ia =  d*inv, ib = -b*inv;
        float ic = -c*inv, id =  a*inv;
        g_p.minv[t][0] = ia; g_p.minv[t][1] = ib; g_p.minv[t][2] = -(ia*tx + ib*ty);
        g_p.minv[t][3] = ic; g_p.minv[t][4] = id; g_p.minv[t][5] = -(ic*tx + id*ty);
        g_p.minv[t][6] = 0.f; g_p.minv[t][7] = 0.f;
    }
    // w1: one thread per (o,c); both halves.  t in [32, 288)
    if (t >= 32 && t < 288) {
        int idx = t - 32, o = idx >> 4, c2 = idx & 15;
        float sc = g1[o] * rsqrtf(rv1[o] + BN_EPS);
        g_p.w1nb[o][c2] = w1[o*32 + c2]      * sc;
        g_p.w1eg[o][c2] = w1[o*32 + 16 + c2] * sc;
        if (c2 == 0) g_p.b1[o] = (b1[o] - rm1[o]) * sc + be1[o];
    }
    // w2: t in [288, 416)
    if (t >= 288 && t < 416) {
        int idx = t - 288, o = idx >> 4, c2 = idx & 15;
        float sc = g2[o] * rsqrtf(rv2[o] + BN_EPS);
        g_p.w2[o][c2] = w2[o*16 + c2] * sc;
        if (c2 == 0) g_p.b2[o] = (b2[o] - rm2[o]) * sc + be2[o];
    }
    // w3: t in [416, 448)
    if (t >= 416 && t < 448) {
        int idx = t - 416, o = idx >> 3, c2 = idx & 7;
        float sc = g3[o] * rsqrtf(rv3[o] + BN_EPS);
        g_p.w3[o][c2] = w3[o*8 + c2] * sc;
        if (c2 == 0) g_p.b3[o] = (b3[o] - rm3[o]) * sc + be3[o];
    }
    if (t >= 448 && t < 452) g_p.w4[t-448] = w4[t-448];
    if (t == 452) g_p.b4 = b4[0];
    // wm: t in [512, 768)
    if (t >= 512 && t < 768) {
        int idx = t - 512, o = idx >> 4, c2 = idx & 15;
        g_p.wm[o][c2] = wm[o*16 + c2];
        if (c2 == 0) g_p.bm[o] = bm[o];
    }
}

// CHW fp32 -> HWC fp16 transpose.
__global__ __launch_bounds__(256)
void transpose_kernel(const float* __restrict__ x)
{
    int idx = blockIdx.x * 256 + threadIdx.x;   // over L*HW
    int j   = idx >> 16;
    int hw  = idx & (HW - 1);
    const float* base = x + (size_t)j * C * HW + hw;

    __half2 v[8];
    #pragma unroll
    for (int k = 0; k < 8; k++) {
        float a = __ldg(base + (2*k)   * HW);
        float b = __ldg(base + (2*k+1) * HW);
        v[k] = __floats2half2_rn(a, b);
    }
    uint4* dst = reinterpret_cast<uint4*>(g_xt) + (size_t)idx * 2;
    dst[0] = reinterpret_cast<uint4*>(v)[0];
    dst[1] = reinterpret_cast<uint4*>(v)[1];
}

// Accumulate one tap (16 ch as 2 x uint4 of half2) into nb2[8] with weight w.
__device__ __forceinline__ void acc_tap2(uint4 va, uint4 vb, float w, float2* nb2)
{
    float2 wv = make_float2(w, w);
    #pragma unroll
    for (int k = 0; k < 4; k++) {
        float2 f = __half22float2(reinterpret_cast<__half2*>(&va)[k]);
        nb2[k] = ffma2(wv, f, nb2[k]);
    }
    #pragma unroll
    for (int k = 0; k < 4; k++) {
        float2 f = __half22float2(reinterpret_cast<__half2*>(&vb)[k]);
        nb2[4+k] = ffma2(wv, f, nb2[4+k]);
    }
}

// dot of 16-wide weight row (float4-aligned in smem) with packed input pairs.
__device__ __forceinline__ float dot16(const float* row, const float2* in2, float bias)
{
    const float4* wr = reinterpret_cast<const float4*>(row);
    float2 a = make_float2(bias, 0.0f);
    #pragma unroll
    for (int q = 0; q < 4; q++) {
        float4 wv = wr[q];
        a = ffma2(make_float2(wv.x, wv.y), in2[2*q],   a);
        a = ffma2(make_float2(wv.z, wv.w), in2[2*q+1], a);
    }
    return a.x + a.y;
}

__global__ __launch_bounds__(256)
void DiscoNetFusion_kernel(const float* __restrict__ x, float* __restrict__ out)
{
    __shared__ Params sp;
    {
        const float4* src = (const float4*)&g_p;
        float4* dst = (float4*)&sp;
        const int n = sizeof(Params) / 16;
        for (int k = threadIdx.x; k < n; k += blockDim.x) dst[k] = src[k];
    }
    __syncthreads();

    const int i  = blockIdx.y;                          // ego agent
    const int hw = blockIdx.x * blockDim.x + threadIdx.x;
    const float wf = (float)(hw & (W-1));
    const float hf = (float)(hw >> 8);

    // ---- ego precompute: w1eg @ x_i + b1 ----
    float ego[16];
    {
        float2 xi2[8];
        #pragma unroll
        for (int c = 0; c < 8; c++) {
            xi2[c].x = x[(i*C + 2*c  )*HW + hw];
            xi2[c].y = x[(i*C + 2*c+1)*HW + hw];
        }
        #pragma unroll
        for (int o = 0; o < 16; o++)
            ego[o] = dot16(sp.w1eg[o], xi2, sp.b1[o]);
    }

    // ---- online softmax state over j ----
    float mrun = -1e30f, srun = 0.0f;
    float2 acc2[8];
    #pragma unroll
    for (int k = 0; k < 8; k++) acc2[k] = make_float2(0.f, 0.f);

    #pragma unroll 1
    for (int j = 0; j < L; j++) {
        const float* mv = sp.minv[j*L + i];
        float sx = fmaf(mv[0], wf, fmaf(mv[1], hf, mv[2]));
        float sy = fmaf(mv[3], wf, fmaf(mv[4], hf, mv[5]));
        float x0f = floorf(sx), y0f = floorf(sy);
        float fx = sx - x0f, fy = sy - y0f;
        float w00 = (1.0f-fx)*(1.0f-fy), w01 = fx*(1.0f-fy);
        float w10 = (1.0f-fx)*fy,        w11 = fx*fy;
        int x0 = (int)x0f, y0 = (int)y0f;
        bool vx0 = (x0   >= 0) && (x0   <= W-1);
        bool vx1 = (x0+1 >= 0) && (x0+1 <= W-1);
        bool vy0 = (y0   >= 0) && (y0   <= H-1);
        bool vy1 = (y0+1 >= 0) && (y0+1 <= H-1);
        if (!(vx0 && vy0)) w00 = 0.0f;
        if (!(vx1 && vy0)) w01 = 0.0f;
        if (!(vx0 && vy1)) w10 = 0.0f;
        if (!(vx1 && vy1)) w11 = 0.0f;
        int xi0 = min(max(x0,   0), W-1), xi1 = min(max(x0+1, 0), W-1);
        int yi0 = min(max(y0,   0), H-1), yi1 = min(max(y0+1, 0), H-1);

        const uint4* jb = reinterpret_cast<const uint4*>(g_xt + (size_t)j * HW * 8);
        const uint4* p00 = jb + (size_t)(yi0*W + xi0) * 2;
        const uint4* p01 = jb + (size_t)(yi0*W + xi1) * 2;
        const uint4* p10 = jb + (size_t)(yi1*W + xi0) * 2;
        const uint4* p11 = jb + (size_t)(yi1*W + xi1) * 2;
        uint4 t00a = __ldg(p00),     t00b = __ldg(p00 + 1);
        uint4 t01a = __ldg(p01),     t01b = __ldg(p01 + 1);
        uint4 t10a = __ldg(p10),     t10b = __ldg(p10 + 1);
        uint4 t11a = __ldg(p11),     t11b = __ldg(p11 + 1);

        float2 nb2[8];
        #pragma unroll
        for (int k = 0; k < 8; k++) nb2[k] = make_float2(0.f, 0.f);
        acc_tap2(t00a, t00b, w00, nb2);
        acc_tap2(t01a, t01b, w01, nb2);
        acc_tap2(t10a, t10b, w10, nb2);
        acc_tap2(t11a, t11b, w11, nb2);

        // ---- tiny MLP -> logit (packed f32x2, LDS.128 weights) ----
        float2 h1p[8];
        #pragma unroll
        for (int o = 0; o < 8; o++) {
            float a = fmaxf(dot16(sp.w1nb[2*o],   nb2, ego[2*o]),   0.0f);
            float b = fmaxf(dot16(sp.w1nb[2*o+1], nb2, ego[2*o+1]), 0.0f);
            h1p[o] = make_float2(a, b);
        }
        float2 h2p[4];
        #pragma unroll
        for (int o = 0; o < 4; o++) {
            float a = fmaxf(dot16(sp.w2[2*o],   h1p, sp.b2[2*o]),   0.0f);
            float b = fmaxf(dot16(sp.w2[2*o+1], h1p, sp.b2[2*o+1]), 0.0f);
            h2p[o] = make_float2(a, b);
        }
        float2 h3p[2];
        #pragma unroll
        for (int o = 0; o < 4; o++) {
            const float4* wr = reinterpret_cast<const float4*>(sp.w3[o]);
            float2 a = make_float2(sp.b3[o], 0.0f);
            float4 w0 = wr[0], w1v = wr[1];
            a = ffma2(make_float2(w0.x,  w0.y),  h2p[0], a);
            a = ffma2(make_float2(w0.z,  w0.w),  h2p[1], a);
            a = ffma2(make_float2(w1v.x, w1v.y), h2p[2], a);
            a = ffma2(make_float2(w1v.z, w1v.w), h2p[3], a);
            float v = fmaxf(a.x + a.y, 0.0f);
            if (o & 1) h3p[o>>1].y = v; else h3p[o>>1].x = v;
        }
        float2 lg2 = make_float2(sp.b4, 0.0f);
        lg2 = ffma2(make_float2(sp.w4[0], sp.w4[1]), h3p[0], lg2);
        lg2 = ffma2(make_float2(sp.w4[2], sp.w4[3]), h3p[1], lg2);
        float lg = fmaxf(lg2.x + lg2.y, 0.0f);

        // ---- online softmax accumulate (packed) ----
        float mn  = fmaxf(mrun, lg);
        float scl = __expf(mrun - mn);
        float p   = __expf(lg - mn);
        srun = srun * scl + p;
        float2 sv = make_float2(scl, scl), pv = make_float2(p, p);
        #pragma unroll
        for (int k = 0; k < 8; k++)
            acc2[k] = ffma2(acc2[k], sv, fmul2(pv, nb2[k]));
        mrun = mn;
    }

    const float invs = 1.0f / srun;
    float2 iv = make_float2(invs, invs);
    #pragma unroll
    for (int k = 0; k < 8; k++) acc2[k] = fmul2(acc2[k], iv);

    // ---- final 16x16 channel mix + bias ----
    #pragma unroll
    for (int o = 0; o < 16; o++)
        out[(i*C + o)*HW + hw] = dot16(sp.wm[o], acc2, sp.bm[o]);
}

extern "C" void kernel_launch(void* const* d_in, const int* in_sizes, int n_in,
                              void* d_out, int out_size)
{
    (void)in_sizes; (void)n_in; (void)out_size;
    const float* x   = (const float*)d_in[0];
    // d_in[1] = record_len (unused)
    const float* ptm = (const float*)d_in[2];

    prep_kernel<<<1, 1024>>>(ptm,
        (const float*)d_in[3],  (const float*)d_in[4],  (const float*)d_in[5],
        (const float*)d_in[6],  (const float*)d_in[7],  (const float*)d_in[8],
        (const float*)d_in[9],  (const float*)d_in[10], (const float*)d_in[11],
        (const float*)d_in[12], (const float*)d_in[13], (const float*)d_in[14],
        (const float*)d_in[15], (const float*)d_in[16], (const float*)d_in[17],
        (const float*)d_in[18], (const float*)d_in[19], (const float*)d_in[20],
        (const float*)d_in[21], (const float*)d_in[22],
        (const float*)d_in[23], (const float*)d_in[24]);

    transpose_kernel<<<(L*HW)/256, 256>>>(x);

    dim3 grid(HW / 256, L);
    DiscoNetFusion_kernel<<<grid, 256>>>(x, (float*)d_out);
}